// round 1
// baseline (speedup 1.0000x reference)
#include <cuda_runtime.h>
#include <math.h>

// ---------------------------------------------------------------------------
// GCN_45921790329163: 2-layer LSTM (N=4096 batch, T=512, H=64) ->
// Pearson-corr adjacency -> 2-layer GCN -> linear classifier.
// ---------------------------------------------------------------------------

#define DEV_INLINE __device__ __forceinline__

constexpr int N_   = 4096;
constexpr int T_   = 512;
constexpr int H_   = 64;
constexpr int G_   = 256;   // 4*H gates
constexpr int F_   = 16;
constexpr int HID_ = 256;
constexpr int NC_  = 10;

constexpr int R_      = 32;   // batch rows per CTA (LSTM)
constexpr int RP_     = 16;   // float2 row-pairs
constexpr int INROW_  = 18;   // ull per k-row (16 data + 2 pad)
constexpr int INROWF_ = 36;   // floats per k-row

// --------------------------- scratch (device globals) ----------------------
__device__ float g_h0[(size_t)T_ * N_ * H_];   // layer0 hidden seq (512 MB)
__device__ float g_xs[(size_t)N_ * T_];        // h1[t][n][0] transposed -> (N,T)
__device__ float g_adj[(size_t)N_ * N_];       // corr + I (64 MB)
__device__ float g_mu[N_];
__device__ float g_sd[N_];
__device__ float g_d[N_];
__device__ float g_y[N_ * HID_];
__device__ float g_z[N_ * HID_];

typedef unsigned long long ull;

DEV_INLINE void fma2(ull& acc, ull a, ull b) {
    asm("fma.rn.f32x2 %0, %1, %2, %3;" : "=l"(acc) : "l"(a), "l"(b), "l"(acc));
}
DEV_INLINE ull pack2(float x) {
    ull r; asm("mov.b64 %0, {%1, %1};" : "=l"(r) : "f"(x)); return r;
}
DEV_INLINE float2 unpack2(ull v) {
    float2 f; asm("mov.b64 {%0, %1}, %2;" : "=f"(f.x), "=f"(f.y) : "l"(v)); return f;
}

DEV_INLINE float sigf(float x) { return 1.0f / (1.0f + __expf(-x)); }
DEV_INLINE float tanh_f(float x) {
    float a = fabsf(x);
    float e = __expf(-2.0f * a);
    float t = (1.0f - e) / (1.0f + e);
    return copysignf(t, x);
}

// --------------------------- LSTM kernel -----------------------------------
// One CTA owns R_=32 batch rows for ALL T timesteps (batch rows independent).
// in2f smem holds [x_t | h] as float pairs: in2f[k*36 + r], k in [0,KIN).
// Each thread computes 2 gate columns x 16 rows with packed f32x2 FMAs.
template <int KIN, int LAYER>
__global__ __launch_bounds__(256, 1)
void lstm_kernel(const float* __restrict__ src,       // layer0: features (N,16,T)
                 const float* __restrict__ w_ih,
                 const float* __restrict__ w_hh,
                 const float* __restrict__ b_ih,
                 const float* __restrict__ b_hh)
{
    constexpr int KI   = KIN - H_;   // input width (16 or 64)
    constexpr int KOFF = KI;         // where h lives in in2f

    extern __shared__ float smem[];
    float* Wt    = smem;                       // [KIN][256] transposed weights
    float* in2f  = Wt + KIN * G_;              // [KIN][36] (padded row of 32)
    ull*   in2   = (ull*)in2f;
    float* gates = in2f + KIN * INROWF_;       // [32][256]
    float* bias  = gates + R_ * G_;            // [256]

    const int tid = threadIdx.x;
    const int n0  = blockIdx.x * R_;

    // ---- fill transposed combined weights Wt[k][g] ----
    for (int idx = tid; idx < KIN * G_; idx += 256) {
        int k = idx >> 8, g = idx & 255;
        float w = (k < KI) ? w_ih[g * KI + k] : w_hh[g * H_ + (k - KI)];
        Wt[idx] = w;
    }
    if (tid < G_) bias[tid] = b_ih[tid] + b_hh[tid];
    for (int idx = tid; idx < KIN * INROWF_; idx += 256) in2f[idx] = 0.0f;
    __syncthreads();

    // ---- stage input for t = 0 ----
    float  xv0 = 0.f, xv1 = 0.f;
    float4 hv0 = make_float4(0, 0, 0, 0), hv1 = hv0;
    if constexpr (LAYER == 0) {
        int e0 = tid, e1 = tid + 256;
        xv0 = src[((size_t)(n0 + (e0 >> 4)) * F_ + (e0 & 15)) * T_ + 0];
        xv1 = src[((size_t)(n0 + (e1 >> 4)) * F_ + (e1 & 15)) * T_ + 0];
        in2f[(e0 & 15) * INROWF_ + (e0 >> 4)] = xv0;
        in2f[(e1 & 15) * INROWF_ + (e1 >> 4)] = xv1;
    } else {
        const float4* s4 = (const float4*)(g_h0 + ((size_t)0 * N_ + n0) * H_);
        hv0 = s4[tid]; hv1 = s4[tid + 256];
        int lin = tid * 4;       int r = lin >> 6, k = lin & 63;
        in2f[(k + 0) * INROWF_ + r] = hv0.x; in2f[(k + 1) * INROWF_ + r] = hv0.y;
        in2f[(k + 2) * INROWF_ + r] = hv0.z; in2f[(k + 3) * INROWF_ + r] = hv0.w;
        lin = (tid + 256) * 4;   r = lin >> 6; k = lin & 63;
        in2f[(k + 0) * INROWF_ + r] = hv1.x; in2f[(k + 1) * INROWF_ + r] = hv1.y;
        in2f[(k + 2) * INROWF_ + r] = hv1.z; in2f[(k + 3) * INROWF_ + r] = hv1.w;
    }
    __syncthreads();

    // phase1 thread mapping: 2 gate cols (g0,g0+1) x 16 rows (half rh)
    const int g0 = (tid & 127) * 2;
    const int rh = tid >> 7;          // row half: 0 or 1
    const int rbase = rh * 16;
    // phase2 thread mapping: unit u, rows grp*8 .. grp*8+7
    const int grp = tid >> 6;
    const int u   = tid & 63;

    float c_reg[8];
#pragma unroll
    for (int p = 0; p < 8; p++) c_reg[p] = 0.0f;

    for (int t = 0; t < T_; t++) {
        // ---- prefetch next step input (consumed after phase1) ----
        if (t + 1 < T_) {
            if constexpr (LAYER == 0) {
                int e0 = tid, e1 = tid + 256;
                xv0 = src[((size_t)(n0 + (e0 >> 4)) * F_ + (e0 & 15)) * T_ + t + 1];
                xv1 = src[((size_t)(n0 + (e1 >> 4)) * F_ + (e1 & 15)) * T_ + t + 1];
            } else {
                const float4* s4 = (const float4*)(g_h0 + ((size_t)(t + 1) * N_ + n0) * H_);
                hv0 = s4[tid]; hv1 = s4[tid + 256];
            }
        }

        // ---- phase 1: gates = bias + Wc^T [x|h] (packed f32x2) ----
        ull acc0[8], acc1[8];
        {
            ull b0 = pack2(bias[g0]), b1 = pack2(bias[g0 + 1]);
#pragma unroll
            for (int q = 0; q < 8; q++) { acc0[q] = b0; acc1[q] = b1; }
        }
#pragma unroll 2
        for (int k = 0; k < KIN; k++) {
            float2 w = *(const float2*)&Wt[k * G_ + g0];
            ull w20 = pack2(w.x), w21 = pack2(w.y);
            const ulonglong2* row = (const ulonglong2*)(in2 + k * INROW_) + rh * 4;
#pragma unroll
            for (int q = 0; q < 4; q++) {
                ulonglong2 v = row[q];
                fma2(acc0[2 * q],     v.x, w20);
                fma2(acc0[2 * q + 1], v.y, w20);
                fma2(acc1[2 * q],     v.x, w21);
                fma2(acc1[2 * q + 1], v.y, w21);
            }
        }
#pragma unroll
        for (int q = 0; q < 8; q++) {
            float2 f0 = unpack2(acc0[q]);
            float2 f1 = unpack2(acc1[q]);
            *(float2*)&gates[(rbase + 2 * q)     * G_ + g0] = make_float2(f0.x, f1.x);
            *(float2*)&gates[(rbase + 2 * q + 1) * G_ + g0] = make_float2(f0.y, f1.y);
        }
        __syncthreads();

        // ---- phase 2: activations, state update ----
#pragma unroll
        for (int p = 0; p < 8; p++) {
            int r = grp * 8 + p;
            const float* gr = gates + r * G_;
            float gi = gr[u], gf = gr[H_ + u], gg = gr[2 * H_ + u], go = gr[3 * H_ + u];
            float c = sigf(gf) * c_reg[p] + sigf(gi) * tanh_f(gg);
            c_reg[p] = c;
            float h = sigf(go) * tanh_f(c);
            in2f[(KOFF + u) * INROWF_ + r] = h;
            if constexpr (LAYER == 0) {
                g_h0[((size_t)t * N_ + n0 + r) * H_ + u] = h;
            } else {
                if (u == 0) g_xs[(size_t)(n0 + r) * T_ + t] = h;
            }
        }
        // ---- commit prefetched input for t+1 ----
        if (t + 1 < T_) {
            if constexpr (LAYER == 0) {
                int e0 = tid, e1 = tid + 256;
                in2f[(e0 & 15) * INROWF_ + (e0 >> 4)] = xv0;
                in2f[(e1 & 15) * INROWF_ + (e1 >> 4)] = xv1;
            } else {
                int lin = tid * 4;       int r = lin >> 6, k = lin & 63;
                in2f[(k + 0) * INROWF_ + r] = hv0.x; in2f[(k + 1) * INROWF_ + r] = hv0.y;
                in2f[(k + 2) * INROWF_ + r] = hv0.z; in2f[(k + 3) * INROWF_ + r] = hv0.w;
                lin = (tid + 256) * 4;   r = lin >> 6; k = lin & 63;
                in2f[(k + 0) * INROWF_ + r] = hv1.x; in2f[(k + 1) * INROWF_ + r] = hv1.y;
                in2f[(k + 2) * INROWF_ + r] = hv1.z; in2f[(k + 3) * INROWF_ + r] = hv1.w;
            }
        }
        __syncthreads();
    }
}

// --------------------------- row stats (mu, std) ----------------------------
__global__ __launch_bounds__(256)
void stats_kernel(const float* __restrict__ xs, float* __restrict__ mu,
                  float* __restrict__ sd)
{
    __shared__ float sh[8], sh2[8];
    int n = blockIdx.x, tid = threadIdx.x;
    float s = 0.f, s2 = 0.f;
    for (int t = tid; t < T_; t += 256) {
        float v = xs[(size_t)n * T_ + t];
        s += v; s2 += v * v;
    }
#pragma unroll
    for (int o = 16; o; o >>= 1) {
        s  += __shfl_xor_sync(0xffffffffu, s, o);
        s2 += __shfl_xor_sync(0xffffffffu, s2, o);
    }
    if ((tid & 31) == 0) { sh[tid >> 5] = s; sh2[tid >> 5] = s2; }
    __syncthreads();
    if (tid == 0) {
        float ts = 0.f, ts2 = 0.f;
        for (int w = 0; w < 8; w++) { ts += sh[w]; ts2 += sh2[w]; }
        float m = ts * (1.0f / T_);
        float var = ts2 * (1.0f / T_) - m * m;
        mu[n] = m;
        sd[n] = sqrtf(fmaxf(var, 0.0f));
    }
}

// --------------------------- corr GEMM (X X^T -> adj) -----------------------
__global__ __launch_bounds__(256)
void corr_kernel(const float* __restrict__ X, float* __restrict__ adj,
                 const float* __restrict__ mu, const float* __restrict__ sd)
{
    if (blockIdx.x < blockIdx.y) return;   // symmetric: upper-triangle tiles only
    __shared__ float As[16][68];
    __shared__ float Bs[16][68];
    const int tid = threadIdx.x;
    const int tx = tid & 15, ty = tid >> 4;
    const int row0 = blockIdx.y * 64, col0 = blockIdx.x * 64;
    const int ar = tid >> 2, ac = (tid & 3) << 2;
    float acc[4][4];
#pragma unroll
    for (int i = 0; i < 4; i++)
#pragma unroll
        for (int j = 0; j < 4; j++) acc[i][j] = 0.f;

    for (int k0 = 0; k0 < T_; k0 += 16) {
        float4 a4 = *(const float4*)&X[(size_t)(row0 + ar) * T_ + k0 + ac];
        As[ac + 0][ar] = a4.x; As[ac + 1][ar] = a4.y;
        As[ac + 2][ar] = a4.z; As[ac + 3][ar] = a4.w;
        float4 b4 = *(const float4*)&X[(size_t)(col0 + ar) * T_ + k0 + ac];
        Bs[ac + 0][ar] = b4.x; Bs[ac + 1][ar] = b4.y;
        Bs[ac + 2][ar] = b4.z; Bs[ac + 3][ar] = b4.w;
        __syncthreads();
#pragma unroll
        for (int k = 0; k < 16; k++) {
            float4 av = *(const float4*)&As[k][ty << 2];
            float4 bv = *(const float4*)&Bs[k][tx << 2];
            float a[4] = { av.x, av.y, av.z, av.w };
            float b[4] = { bv.x, bv.y, bv.z, bv.w };
#pragma unroll
            for (int i = 0; i < 4; i++)
#pragma unroll
                for (int j = 0; j < 4; j++) acc[i][j] += a[i] * b[j];
        }
        __syncthreads();
    }
#pragma unroll
    for (int i = 0; i < 4; i++) {
        int gi = row0 + (ty << 2) + i;
        float mi = mu[gi], si = sd[gi];
#pragma unroll
        for (int j = 0; j < 4; j++) {
            int gj = col0 + (tx << 2) + j;
            float cov = acc[i][j] * (1.0f / T_) - mi * mu[gj];
            float den = si * sd[gj];
            float corr = (den == 0.0f) ? 0.0f : cov / den;
            float a = corr + ((gi == gj) ? 1.0f : 0.0f);
            adj[(size_t)gi * N_ + gj] = a;
            adj[(size_t)gj * N_ + gi] = a;
        }
    }
}

// --------------------------- rowsum -> d = rs^-0.5 --------------------------
__global__ __launch_bounds__(256)
void rowsum_kernel(const float* __restrict__ adj, float* __restrict__ dvec)
{
    __shared__ float sh[8];
    int i = blockIdx.x, tid = threadIdx.x;
    float s = 0.f;
    for (int j = tid; j < N_; j += 256) s += adj[(size_t)i * N_ + j];
#pragma unroll
    for (int o = 16; o; o >>= 1) s += __shfl_xor_sync(0xffffffffu, s, o);
    if ((tid & 31) == 0) sh[tid >> 5] = s;
    __syncthreads();
    if (tid == 0) {
        float ts = 0.f;
        for (int w = 0; w < 8; w++) ts += sh[w];
        dvec[i] = (ts > 0.0f) ? (1.0f / sqrtf(ts)) : 0.0f;
    }
}

// --------------------------- tiled GEMM (NN) with epilogues -----------------
// MODE 1: C = d[i] * (A@B)            (pre-scale for D adj D y trick)
// MODE 2: C = relu(d[i] * (A@B) + bias[j])
template <int MODE>
__global__ __launch_bounds__(256)
void gemm_nn(const float* __restrict__ A, const float* __restrict__ B,
             float* __restrict__ C, int M, int N, int K,
             const float* __restrict__ dvec, const float* __restrict__ bias)
{
    __shared__ float As[16][68];
    __shared__ float Bs[16][64];
    const int tid = threadIdx.x;
    const int tx = tid & 15, ty = tid >> 4;
    const int row0 = blockIdx.y * 64, col0 = blockIdx.x * 64;
    const int ar = tid >> 2, ac = (tid & 3) << 2;
    const int br = tid >> 4, bc = (tid & 15) << 2;
    float acc[4][4];
#pragma unroll
    for (int i = 0; i < 4; i++)
#pragma unroll
        for (int j = 0; j < 4; j++) acc[i][j] = 0.f;

    for (int k0 = 0; k0 < K; k0 += 16) {
        float4 a4 = *(const float4*)&A[(size_t)(row0 + ar) * K + k0 + ac];
        As[ac + 0][ar] = a4.x; As[ac + 1][ar] = a4.y;
        As[ac + 2][ar] = a4.z; As[ac + 3][ar] = a4.w;
        *(float4*)&Bs[br][bc] = *(const float4*)&B[(size_t)(k0 + br) * N + col0 + bc];
        __syncthreads();
#pragma unroll
        for (int k = 0; k < 16; k++) {
            float4 av = *(const float4*)&As[k][ty << 2];
            float4 bv = *(const float4*)&Bs[k][tx << 2];
            float a[4] = { av.x, av.y, av.z, av.w };
            float b[4] = { bv.x, bv.y, bv.z, bv.w };
#pragma unroll
            for (int i = 0; i < 4; i++)
#pragma unroll
                for (int j = 0; j < 4; j++) acc[i][j] += a[i] * b[j];
        }
        __syncthreads();
    }
#pragma unroll
    for (int i = 0; i < 4; i++) {
        int gi = row0 + (ty << 2) + i;
        float dv = (MODE >= 1) ? dvec[gi] : 1.0f;
#pragma unroll
        for (int j = 0; j < 4; j++) {
            int gj = col0 + (tx << 2) + j;
            float v = acc[i][j];
            if (MODE == 1) v = dv * v;
            if (MODE == 2) { v = dv * v + bias[gj]; v = fmaxf(v, 0.0f); }
            C[(size_t)gi * N + gj] = v;
        }
    }
}

// --------------------------- classifier -------------------------------------
__global__ void clf_kernel(const float* __restrict__ z, const float* __restrict__ w,
                           const float* __restrict__ b, float* __restrict__ out)
{
    int idx = blockIdx.x * blockDim.x + threadIdx.x;
    if (idx >= N_ * NC_) return;
    int n = idx / NC_, c = idx - n * NC_;
    float s = b[c];
    const float* zr = z + (size_t)n * HID_;
#pragma unroll 8
    for (int h = 0; h < HID_; h++) s += zr[h] * w[h * NC_ + c];
    out[idx] = s;
}

// --------------------------- launch ------------------------------------------
extern "C" void kernel_launch(void* const* d_in, const int* in_sizes, int n_in,
                              void* d_out, int out_size)
{
    const float* features = (const float*)d_in[0];
    const float* w_ih0 = (const float*)d_in[1];
    const float* w_hh0 = (const float*)d_in[2];
    const float* b_ih0 = (const float*)d_in[3];
    const float* b_hh0 = (const float*)d_in[4];
    const float* w_ih1 = (const float*)d_in[5];
    const float* w_hh1 = (const float*)d_in[6];
    const float* b_ih1 = (const float*)d_in[7];
    const float* b_hh1 = (const float*)d_in[8];
    const float* gc1_w = (const float*)d_in[9];
    const float* gc1_b = (const float*)d_in[10];
    const float* gc2_w = (const float*)d_in[11];
    const float* gc2_b = (const float*)d_in[12];
    const float* clf_w = (const float*)d_in[13];
    const float* clf_b = (const float*)d_in[14];
    float* out = (float*)d_out;

    float *p_xs, *p_adj, *p_mu, *p_sd, *p_d, *p_y, *p_z;
    cudaGetSymbolAddress((void**)&p_xs,  g_xs);
    cudaGetSymbolAddress((void**)&p_adj, g_adj);
    cudaGetSymbolAddress((void**)&p_mu,  g_mu);
    cudaGetSymbolAddress((void**)&p_sd,  g_sd);
    cudaGetSymbolAddress((void**)&p_d,   g_d);
    cudaGetSymbolAddress((void**)&p_y,   g_y);
    cudaGetSymbolAddress((void**)&p_z,   g_z);

    const int smem0 = (80  * G_ + 80  * INROWF_ + R_ * G_ + G_) * 4;  // 127232 B
    const int smem1 = (128 * G_ + 128 * INROWF_ + R_ * G_ + G_) * 4;  // 183296 B
    cudaFuncSetAttribute((const void*)lstm_kernel<80, 0>,
                         cudaFuncAttributeMaxDynamicSharedMemorySize, smem0);
    cudaFuncSetAttribute((const void*)lstm_kernel<128, 1>,
                         cudaFuncAttributeMaxDynamicSharedMemorySize, smem1);

    // LSTM layer 0 (input: features) -> g_h0
    lstm_kernel<80, 0><<<N_ / R_, 256, smem0>>>(features, w_ih0, w_hh0, b_ih0, b_hh0);
    // LSTM layer 1 (input: g_h0) -> g_xs (channel 0 only)
    lstm_kernel<128, 1><<<N_ / R_, 256, smem1>>>(nullptr, w_ih1, w_hh1, b_ih1, b_hh1);

    // adjacency
    stats_kernel<<<N_, 256>>>(p_xs, p_mu, p_sd);
    corr_kernel<<<dim3(N_ / 64, N_ / 64), 256>>>(p_xs, p_adj, p_mu, p_sd);
    rowsum_kernel<<<N_, 256>>>(p_adj, p_d);

    // GCN: dad@M = D adj D M -> fold both D scalings into GEMM epilogues
    gemm_nn<1><<<dim3(HID_ / 64, N_ / 64), 256>>>(p_xs,  gc1_w, p_y, N_, HID_, T_,   p_d, nullptr);
    gemm_nn<2><<<dim3(HID_ / 64, N_ / 64), 256>>>(p_adj, p_y,   p_z, N_, HID_, N_,   p_d, gc1_b);
    gemm_nn<1><<<dim3(HID_ / 64, N_ / 64), 256>>>(p_z,   gc2_w, p_y, N_, HID_, HID_, p_d, nullptr);
    gemm_nn<2><<<dim3(HID_ / 64, N_ / 64), 256>>>(p_adj, p_y,   p_z, N_, HID_, N_,   p_d, gc2_b);

    // classifier
    clf_kernel<<<(N_ * NC_ + 255) / 256, 256>>>(p_z, clf_w, clf_b, out);
}

// round 2
// speedup vs baseline: 1.9810x; 1.9810x over previous
#include <cuda_runtime.h>
#include <math.h>

// ---------------------------------------------------------------------------
// GCN_45921790329163: 2-layer LSTM (N=4096 batch, T=512, H=64) ->
// Pearson-corr adjacency -> 2-layer GCN -> linear classifier.
// R1: LSTM kernels moved to 512 threads/CTA (4 warps/SMSP) for latency hiding.
// ---------------------------------------------------------------------------

#define DEV_INLINE __device__ __forceinline__

constexpr int N_   = 4096;
constexpr int T_   = 512;
constexpr int H_   = 64;
constexpr int G_   = 256;   // 4*H gates
constexpr int F_   = 16;
constexpr int HID_ = 256;
constexpr int NC_  = 10;

constexpr int R_      = 32;   // batch rows per CTA (LSTM)
constexpr int INROW_  = 18;   // ull per k-row (16 data + 2 pad)
constexpr int INROWF_ = 36;   // floats per k-row

// --------------------------- scratch (device globals) ----------------------
__device__ float g_h0[(size_t)T_ * N_ * H_];   // layer0 hidden seq (512 MB)
__device__ float g_xs[(size_t)N_ * T_];        // h1[t][n][0] transposed -> (N,T)
__device__ float g_adj[(size_t)N_ * N_];       // corr + I (64 MB)
__device__ float g_mu[N_];
__device__ float g_sd[N_];
__device__ float g_d[N_];
__device__ float g_y[N_ * HID_];
__device__ float g_z[N_ * HID_];

typedef unsigned long long ull;

DEV_INLINE void fma2(ull& acc, ull a, ull b) {
    asm("fma.rn.f32x2 %0, %1, %2, %3;" : "=l"(acc) : "l"(a), "l"(b), "l"(acc));
}
DEV_INLINE ull pack2(float x) {
    ull r; asm("mov.b64 %0, {%1, %1};" : "=l"(r) : "f"(x)); return r;
}
DEV_INLINE float2 unpack2(ull v) {
    float2 f; asm("mov.b64 {%0, %1}, %2;" : "=f"(f.x), "=f"(f.y) : "l"(v)); return f;
}

DEV_INLINE float sigf(float x) { return 1.0f / (1.0f + __expf(-x)); }
DEV_INLINE float tanh_f(float x) {
    float a = fabsf(x);
    float e = __expf(-2.0f * a);
    float t = (1.0f - e) / (1.0f + e);
    return copysignf(t, x);
}

// --------------------------- LSTM kernel -----------------------------------
// One CTA owns R_=32 batch rows for ALL T timesteps (batch rows independent).
// 512 threads. Phase1: thread = 2 gate cols x 8 rows (packed f32x2 FMA).
// Phase2: thread = 1 unit x 4 rows (activations + state update).
template <int KIN, int LAYER>
__global__ __launch_bounds__(512, 1)
void lstm_kernel(const float* __restrict__ src,       // layer0: features (N,16,T)
                 const float* __restrict__ w_ih,
                 const float* __restrict__ w_hh,
                 const float* __restrict__ b_ih,
                 const float* __restrict__ b_hh)
{
    constexpr int KI = KIN - H_;     // input width (16 or 64); h lives at rows KI..

    extern __shared__ float smem[];
    float* Wt    = smem;                       // [KIN][256] transposed weights
    float* in2f  = Wt + KIN * G_;              // [KIN][36] (32 rows + pad)
    ull*   in2   = (ull*)in2f;
    float* gates = in2f + KIN * INROWF_;       // [32][256]
    float* bias  = gates + R_ * G_;            // [256]

    const int tid = threadIdx.x;
    const int n0  = blockIdx.x * R_;

    // ---- fill transposed combined weights Wt[k][g] ----
    for (int idx = tid; idx < KIN * G_; idx += 512) {
        int k = idx >> 8, g = idx & 255;
        Wt[idx] = (k < KI) ? w_ih[g * KI + k] : w_hh[g * H_ + (k - KI)];
    }
    if (tid < G_) bias[tid] = b_ih[tid] + b_hh[tid];
    for (int idx = tid; idx < KIN * INROWF_; idx += 512) in2f[idx] = 0.0f;
    __syncthreads();

    // ---- stage input for t = 0 ----
    float  xv = 0.f;
    float4 hv = make_float4(0, 0, 0, 0);
    if constexpr (LAYER == 0) {
        int r = tid >> 4, f = tid & 15;
        xv = src[((size_t)(n0 + r) * F_ + f) * T_ + 0];
        in2f[f * INROWF_ + r] = xv;
    } else {
        hv = ((const float4*)(g_h0 + (size_t)n0 * H_))[tid];
        int lin = tid * 4, r = lin >> 6, k = lin & 63;
        in2f[(k + 0) * INROWF_ + r] = hv.x; in2f[(k + 1) * INROWF_ + r] = hv.y;
        in2f[(k + 2) * INROWF_ + r] = hv.z; in2f[(k + 3) * INROWF_ + r] = hv.w;
    }
    __syncthreads();

    // phase1 mapping: 2 gate cols (g0,g0+1) x 8 rows (quarter qtr)
    const int g0  = (tid & 127) * 2;
    const int qtr = tid >> 7;          // 0..3
    // phase2 mapping: unit u, rows grp*4 .. grp*4+3
    const int grp = tid >> 6;          // 0..7
    const int u   = tid & 63;

    float c_reg[4];
#pragma unroll
    for (int p = 0; p < 4; p++) c_reg[p] = 0.0f;

    for (int t = 0; t < T_; t++) {
        // ---- prefetch next step input (committed after phase1) ----
        if (t + 1 < T_) {
            if constexpr (LAYER == 0) {
                xv = src[((size_t)(n0 + (tid >> 4)) * F_ + (tid & 15)) * T_ + t + 1];
            } else {
                hv = ((const float4*)(g_h0 + ((size_t)(t + 1) * N_ + n0) * H_))[tid];
            }
        }

        // ---- phase 1: gates = bias + Wc^T [x|h] (packed f32x2) ----
        ull acc0[4], acc1[4];
        {
            ull b0 = pack2(bias[g0]), b1 = pack2(bias[g0 + 1]);
#pragma unroll
            for (int q = 0; q < 4; q++) { acc0[q] = b0; acc1[q] = b1; }
        }
#pragma unroll 4
        for (int k = 0; k < KIN; k++) {
            float2 w = *(const float2*)&Wt[k * G_ + g0];
            ull w20 = pack2(w.x), w21 = pack2(w.y);
            const ulonglong2* row = (const ulonglong2*)(in2 + k * INROW_) + qtr * 2;
            ulonglong2 v0 = row[0], v1 = row[1];
            fma2(acc0[0], v0.x, w20); fma2(acc1[0], v0.x, w21);
            fma2(acc0[1], v0.y, w20); fma2(acc1[1], v0.y, w21);
            fma2(acc0[2], v1.x, w20); fma2(acc1[2], v1.x, w21);
            fma2(acc0[3], v1.y, w20); fma2(acc1[3], v1.y, w21);
        }
#pragma unroll
        for (int q = 0; q < 4; q++) {
            float2 f0 = unpack2(acc0[q]);
            float2 f1 = unpack2(acc1[q]);
            *(float2*)&gates[(qtr * 8 + 2 * q)     * G_ + g0] = make_float2(f0.x, f1.x);
            *(float2*)&gates[(qtr * 8 + 2 * q + 1) * G_ + g0] = make_float2(f0.y, f1.y);
        }
        __syncthreads();

        // ---- phase 2: activations, state update ----
#pragma unroll
        for (int p = 0; p < 4; p++) {
            int r = grp * 4 + p;
            const float* gr = gates + r * G_;
            float gi = gr[u], gf = gr[H_ + u], gg = gr[2 * H_ + u], go = gr[3 * H_ + u];
            float c = sigf(gf) * c_reg[p] + sigf(gi) * tanh_f(gg);
            c_reg[p] = c;
            float h = sigf(go) * tanh_f(c);
            in2f[(KI + u) * INROWF_ + r] = h;
            if constexpr (LAYER == 0) {
                g_h0[((size_t)t * N_ + n0 + r) * H_ + u] = h;
            } else {
                if (u == 0) g_xs[(size_t)(n0 + r) * T_ + t] = h;
            }
        }
        // ---- commit prefetched input for t+1 ----
        if (t + 1 < T_) {
            if constexpr (LAYER == 0) {
                in2f[(tid & 15) * INROWF_ + (tid >> 4)] = xv;
            } else {
                int lin = tid * 4, r = lin >> 6, k = lin & 63;
                in2f[(k + 0) * INROWF_ + r] = hv.x; in2f[(k + 1) * INROWF_ + r] = hv.y;
                in2f[(k + 2) * INROWF_ + r] = hv.z; in2f[(k + 3) * INROWF_ + r] = hv.w;
            }
        }
        __syncthreads();
    }
}

// --------------------------- row stats (mu, std) ----------------------------
__global__ __launch_bounds__(256)
void stats_kernel(const float* __restrict__ xs, float* __restrict__ mu,
                  float* __restrict__ sd)
{
    __shared__ float sh[8], sh2[8];
    int n = blockIdx.x, tid = threadIdx.x;
    float s = 0.f, s2 = 0.f;
    for (int t = tid; t < T_; t += 256) {
        float v = xs[(size_t)n * T_ + t];
        s += v; s2 += v * v;
    }
#pragma unroll
    for (int o = 16; o; o >>= 1) {
        s  += __shfl_xor_sync(0xffffffffu, s, o);
        s2 += __shfl_xor_sync(0xffffffffu, s2, o);
    }
    if ((tid & 31) == 0) { sh[tid >> 5] = s; sh2[tid >> 5] = s2; }
    __syncthreads();
    if (tid == 0) {
        float ts = 0.f, ts2 = 0.f;
        for (int w = 0; w < 8; w++) { ts += sh[w]; ts2 += sh2[w]; }
        float m = ts * (1.0f / T_);
        float var = ts2 * (1.0f / T_) - m * m;
        mu[n] = m;
        sd[n] = sqrtf(fmaxf(var, 0.0f));
    }
}

// --------------------------- corr GEMM (X X^T -> adj) -----------------------
__global__ __launch_bounds__(256)
void corr_kernel(const float* __restrict__ X, float* __restrict__ adj,
                 const float* __restrict__ mu, const float* __restrict__ sd)
{
    if (blockIdx.x < blockIdx.y) return;   // symmetric: upper-triangle tiles only
    __shared__ float As[16][68];
    __shared__ float Bs[16][68];
    const int tid = threadIdx.x;
    const int tx = tid & 15, ty = tid >> 4;
    const int row0 = blockIdx.y * 64, col0 = blockIdx.x * 64;
    const int ar = tid >> 2, ac = (tid & 3) << 2;
    float acc[4][4];
#pragma unroll
    for (int i = 0; i < 4; i++)
#pragma unroll
        for (int j = 0; j < 4; j++) acc[i][j] = 0.f;

    for (int k0 = 0; k0 < T_; k0 += 16) {
        float4 a4 = *(const float4*)&X[(size_t)(row0 + ar) * T_ + k0 + ac];
        As[ac + 0][ar] = a4.x; As[ac + 1][ar] = a4.y;
        As[ac + 2][ar] = a4.z; As[ac + 3][ar] = a4.w;
        float4 b4 = *(const float4*)&X[(size_t)(col0 + ar) * T_ + k0 + ac];
        Bs[ac + 0][ar] = b4.x; Bs[ac + 1][ar] = b4.y;
        Bs[ac + 2][ar] = b4.z; Bs[ac + 3][ar] = b4.w;
        __syncthreads();
#pragma unroll
        for (int k = 0; k < 16; k++) {
            float4 av = *(const float4*)&As[k][ty << 2];
            float4 bv = *(const float4*)&Bs[k][tx << 2];
            float a[4] = { av.x, av.y, av.z, av.w };
            float b[4] = { bv.x, bv.y, bv.z, bv.w };
#pragma unroll
            for (int i = 0; i < 4; i++)
#pragma unroll
                for (int j = 0; j < 4; j++) acc[i][j] += a[i] * b[j];
        }
        __syncthreads();
    }
#pragma unroll
    for (int i = 0; i < 4; i++) {
        int gi = row0 + (ty << 2) + i;
        float mi = mu[gi], si = sd[gi];
#pragma unroll
        for (int j = 0; j < 4; j++) {
            int gj = col0 + (tx << 2) + j;
            float cov = acc[i][j] * (1.0f / T_) - mi * mu[gj];
            float den = si * sd[gj];
            float corr = (den == 0.0f) ? 0.0f : cov / den;
            float a = corr + ((gi == gj) ? 1.0f : 0.0f);
            adj[(size_t)gi * N_ + gj] = a;
            adj[(size_t)gj * N_ + gi] = a;
        }
    }
}

// --------------------------- rowsum -> d = rs^-0.5 --------------------------
__global__ __launch_bounds__(256)
void rowsum_kernel(const float* __restrict__ adj, float* __restrict__ dvec)
{
    __shared__ float sh[8];
    int i = blockIdx.x, tid = threadIdx.x;
    float s = 0.f;
    for (int j = tid; j < N_; j += 256) s += adj[(size_t)i * N_ + j];
#pragma unroll
    for (int o = 16; o; o >>= 1) s += __shfl_xor_sync(0xffffffffu, s, o);
    if ((tid & 31) == 0) sh[tid >> 5] = s;
    __syncthreads();
    if (tid == 0) {
        float ts = 0.f;
        for (int w = 0; w < 8; w++) ts += sh[w];
        dvec[i] = (ts > 0.0f) ? (1.0f / sqrtf(ts)) : 0.0f;
    }
}

// --------------------------- tiled GEMM (NN) with epilogues -----------------
// MODE 1: C = d[i] * (A@B)            (pre-scale for D adj D y trick)
// MODE 2: C = relu(d[i] * (A@B) + bias[j])
template <int MODE>
__global__ __launch_bounds__(256)
void gemm_nn(const float* __restrict__ A, const float* __restrict__ B,
             float* __restrict__ C, int M, int N, int K,
             const float* __restrict__ dvec, const float* __restrict__ bias)
{
    __shared__ float As[16][68];
    __shared__ float Bs[16][64];
    const int tid = threadIdx.x;
    const int tx = tid & 15, ty = tid >> 4;
    const int row0 = blockIdx.y * 64, col0 = blockIdx.x * 64;
    const int ar = tid >> 2, ac = (tid & 3) << 2;
    const int br = tid >> 4, bc = (tid & 15) << 2;
    float acc[4][4];
#pragma unroll
    for (int i = 0; i < 4; i++)
#pragma unroll
        for (int j = 0; j < 4; j++) acc[i][j] = 0.f;

    for (int k0 = 0; k0 < K; k0 += 16) {
        float4 a4 = *(const float4*)&A[(size_t)(row0 + ar) * K + k0 + ac];
        As[ac + 0][ar] = a4.x; As[ac + 1][ar] = a4.y;
        As[ac + 2][ar] = a4.z; As[ac + 3][ar] = a4.w;
        *(float4*)&Bs[br][bc] = *(const float4*)&B[(size_t)(k0 + br) * N + col0 + bc];
        __syncthreads();
#pragma unroll
        for (int k = 0; k < 16; k++) {
            float4 av = *(const float4*)&As[k][ty << 2];
            float4 bv = *(const float4*)&Bs[k][tx << 2];
            float a[4] = { av.x, av.y, av.z, av.w };
            float b[4] = { bv.x, bv.y, bv.z, bv.w };
#pragma unroll
            for (int i = 0; i < 4; i++)
#pragma unroll
                for (int j = 0; j < 4; j++) acc[i][j] += a[i] * b[j];
        }
        __syncthreads();
    }
#pragma unroll
    for (int i = 0; i < 4; i++) {
        int gi = row0 + (ty << 2) + i;
        float dv = (MODE >= 1) ? dvec[gi] : 1.0f;
#pragma unroll
        for (int j = 0; j < 4; j++) {
            int gj = col0 + (tx << 2) + j;
            float v = acc[i][j];
            if (MODE == 1) v = dv * v;
            if (MODE == 2) { v = dv * v + bias[gj]; v = fmaxf(v, 0.0f); }
            C[(size_t)gi * N + gj] = v;
        }
    }
}

// --------------------------- classifier -------------------------------------
__global__ void clf_kernel(const float* __restrict__ z, const float* __restrict__ w,
                           const float* __restrict__ b, float* __restrict__ out)
{
    int idx = blockIdx.x * blockDim.x + threadIdx.x;
    if (idx >= N_ * NC_) return;
    int n = idx / NC_, c = idx - n * NC_;
    float s = b[c];
    const float* zr = z + (size_t)n * HID_;
#pragma unroll 8
    for (int h = 0; h < HID_; h++) s += zr[h] * w[h * NC_ + c];
    out[idx] = s;
}

// --------------------------- launch ------------------------------------------
extern "C" void kernel_launch(void* const* d_in, const int* in_sizes, int n_in,
                              void* d_out, int out_size)
{
    const float* features = (const float*)d_in[0];
    const float* w_ih0 = (const float*)d_in[1];
    const float* w_hh0 = (const float*)d_in[2];
    const float* b_ih0 = (const float*)d_in[3];
    const float* b_hh0 = (const float*)d_in[4];
    const float* w_ih1 = (const float*)d_in[5];
    const float* w_hh1 = (const float*)d_in[6];
    const float* b_ih1 = (const float*)d_in[7];
    const float* b_hh1 = (const float*)d_in[8];
    const float* gc1_w = (const float*)d_in[9];
    const float* gc1_b = (const float*)d_in[10];
    const float* gc2_w = (const float*)d_in[11];
    const float* gc2_b = (const float*)d_in[12];
    const float* clf_w = (const float*)d_in[13];
    const float* clf_b = (const float*)d_in[14];
    float* out = (float*)d_out;

    float *p_xs, *p_adj, *p_mu, *p_sd, *p_d, *p_y, *p_z;
    cudaGetSymbolAddress((void**)&p_xs,  g_xs);
    cudaGetSymbolAddress((void**)&p_adj, g_adj);
    cudaGetSymbolAddress((void**)&p_mu,  g_mu);
    cudaGetSymbolAddress((void**)&p_sd,  g_sd);
    cudaGetSymbolAddress((void**)&p_d,   g_d);
    cudaGetSymbolAddress((void**)&p_y,   g_y);
    cudaGetSymbolAddress((void**)&p_z,   g_z);

    const int smem0 = (80  * G_ + 80  * INROWF_ + R_ * G_ + G_) * 4;  // 127232 B
    const int smem1 = (128 * G_ + 128 * INROWF_ + R_ * G_ + G_) * 4;  // 183296 B
    cudaFuncSetAttribute((const void*)lstm_kernel<80, 0>,
                         cudaFuncAttributeMaxDynamicSharedMemorySize, smem0);
    cudaFuncSetAttribute((const void*)lstm_kernel<128, 1>,
                         cudaFuncAttributeMaxDynamicSharedMemorySize, smem1);

    // LSTM layer 0 (input: features) -> g_h0
    lstm_kernel<80, 0><<<N_ / R_, 512, smem0>>>(features, w_ih0, w_hh0, b_ih0, b_hh0);
    // LSTM layer 1 (input: g_h0) -> g_xs (channel 0 only)
    lstm_kernel<128, 1><<<N_ / R_, 512, smem1>>>(nullptr, w_ih1, w_hh1, b_ih1, b_hh1);

    // adjacency
    stats_kernel<<<N_, 256>>>(p_xs, p_mu, p_sd);
    corr_kernel<<<dim3(N_ / 64, N_ / 64), 256>>>(p_xs, p_adj, p_mu, p_sd);
    rowsum_kernel<<<N_, 256>>>(p_adj, p_d);

    // GCN: dad@M = D adj D M -> fold both D scalings into GEMM epilogues
    gemm_nn<1><<<dim3(HID_ / 64, N_ / 64), 256>>>(p_xs,  gc1_w, p_y, N_, HID_, T_,   p_d, nullptr);
    gemm_nn<2><<<dim3(HID_ / 64, N_ / 64), 256>>>(p_adj, p_y,   p_z, N_, HID_, N_,   p_d, gc1_b);
    gemm_nn<1><<<dim3(HID_ / 64, N_ / 64), 256>>>(p_z,   gc2_w, p_y, N_, HID_, HID_, p_d, nullptr);
    gemm_nn<2><<<dim3(HID_ / 64, N_ / 64), 256>>>(p_adj, p_y,   p_z, N_, HID_, N_,   p_d, gc2_b);

    // classifier
    clf_kernel<<<(N_ * NC_ + 255) / 256, 256>>>(p_z, clf_w, clf_b, out);
}

// round 3
// speedup vs baseline: 2.0681x; 1.0440x over previous
#include <cuda_runtime.h>
#include <math.h>

// ---------------------------------------------------------------------------
// GCN_45921790329163: 2-layer LSTM (N=4096 batch, T=512, H=64) ->
// Pearson-corr adjacency -> 2-layer GCN -> linear classifier.
// R2: fused LSTM phases (gate-interleaved weights), single barrier/step via
//     ping-pong input buffer; f32x2-packed GCN GEMMs.
// ---------------------------------------------------------------------------

#define DEV_INLINE __device__ __forceinline__

constexpr int N_   = 4096;
constexpr int T_   = 512;
constexpr int H_   = 64;
constexpr int G_   = 256;   // 4*H gates
constexpr int F_   = 16;
constexpr int HID_ = 256;
constexpr int NC_  = 10;

constexpr int R_      = 32;   // batch rows per CTA (LSTM)
constexpr int INROW_  = 18;   // ull per k-row (16 data + 2 pad)
constexpr int INROWF_ = 36;   // floats per k-row

// --------------------------- scratch (device globals) ----------------------
__device__ float g_h0[(size_t)T_ * N_ * H_];   // layer0 hidden seq (512 MB)
__device__ float g_xs[(size_t)N_ * T_];        // h1[t][n][0] transposed -> (N,T)
__device__ float g_adj[(size_t)N_ * N_];       // corr + I (64 MB)
__device__ float g_mu[N_];
__device__ float g_sd[N_];
__device__ float g_d[N_];
__device__ float g_y[N_ * HID_];
__device__ float g_z[N_ * HID_];

typedef unsigned long long ull;

DEV_INLINE void fma2(ull& acc, ull a, ull b) {
    asm("fma.rn.f32x2 %0, %1, %2, %3;" : "=l"(acc) : "l"(a), "l"(b), "l"(acc));
}
DEV_INLINE ull pack2(float x) {
    ull r; asm("mov.b64 %0, {%1, %1};" : "=l"(r) : "f"(x)); return r;
}
DEV_INLINE ull packab(float lo, float hi) {
    ull r; asm("mov.b64 %0, {%1, %2};" : "=l"(r) : "f"(lo), "f"(hi)); return r;
}
DEV_INLINE float2 unpack2(ull v) {
    float2 f; asm("mov.b64 {%0, %1}, %2;" : "=f"(f.x), "=f"(f.y) : "l"(v)); return f;
}

DEV_INLINE float sigf(float x) { return 1.0f / (1.0f + __expf(-x)); }
DEV_INLINE float tanh_f(float x) {
    float a = fabsf(x);
    float e = __expf(-2.0f * a);
    float t = (1.0f - e) / (1.0f + e);
    return copysignf(t, x);
}

// --------------------------- LSTM kernel -----------------------------------
// One CTA owns R_=32 batch rows for ALL T timesteps. 512 threads.
// Thread (u = tid>>3, rg = tid&7) computes gates i,f,g,o of unit u for rows
// 4rg..4rg+3 (packed f32x2), then does the activations + state update for
// exactly those (unit,row) cells. Weights stored gate-interleaved:
// Wt2[k][4u+j] = W[gate j, unit u][k]. Input buffer in2f is ping-ponged so a
// single __syncthreads per timestep suffices.
template <int KIN, int LAYER>
__global__ __launch_bounds__(512, 1)
void lstm_kernel(const float* __restrict__ src,       // layer0: features (N,16,T)
                 const float* __restrict__ w_ih,
                 const float* __restrict__ w_hh,
                 const float* __restrict__ b_ih,
                 const float* __restrict__ b_hh)
{
    constexpr int KI = KIN - H_;     // input width (16 or 64); h lives at rows KI..

    extern __shared__ float smem[];
    float* Wt2  = smem;                        // [KIN][256] gate-interleaved
    float* in2f = Wt2 + KIN * G_;              // 2 x [KIN][36] ping-pong

    const int tid = threadIdx.x;
    const int n0  = blockIdx.x * R_;
    const int u   = tid >> 3;        // unit 0..63
    const int rg  = tid & 7;         // row group: rows 4rg..4rg+3

    // ---- fill gate-interleaved weights Wt2[k][4u+j] ----
    for (int idx = tid; idx < KIN * G_; idx += 512) {
        int k = idx >> 8, c = idx & 255;
        int uu = c >> 2, j = c & 3;
        int row = j * H_ + uu;                 // torch gate-major row
        Wt2[idx] = (k < KI) ? w_ih[row * KI + k] : w_hh[row * H_ + (k - KI)];
    }
    // zero both ping-pong buffers
    for (int idx = tid; idx < 2 * KIN * INROWF_; idx += 512) in2f[idx] = 0.0f;

    // bias in registers (4 gates of unit u)
    float bj[4];
#pragma unroll
    for (int j = 0; j < 4; j++) bj[j] = b_ih[j * H_ + u] + b_hh[j * H_ + u];

    __syncthreads();

    // ---- stage x(0) into buffer 0 ----
    if constexpr (LAYER == 0) {
        int r = tid >> 4, f = tid & 15;
        in2f[f * INROWF_ + r] = src[((size_t)(n0 + r) * F_ + f) * T_ + 0];
    } else {
        float4 hv = ((const float4*)(g_h0 + (size_t)n0 * H_))[tid];
        int lin = tid * 4, r = lin >> 6, k = lin & 63;
        in2f[(k + 0) * INROWF_ + r] = hv.x; in2f[(k + 1) * INROWF_ + r] = hv.y;
        in2f[(k + 2) * INROWF_ + r] = hv.z; in2f[(k + 3) * INROWF_ + r] = hv.w;
    }
    __syncthreads();

    float c_reg[4];
#pragma unroll
    for (int p = 0; p < 4; p++) c_reg[p] = 0.0f;

    float  xv = 0.f;
    float4 hv = make_float4(0, 0, 0, 0);

    for (int t = 0; t < T_; t++) {
        const float* cur = in2f + (t & 1) * KIN * INROWF_;
        float*       nxt = in2f + ((t + 1) & 1) * KIN * INROWF_;
        const ull*   in2c = (const ull*)cur;

        // ---- prefetch x(t+1) (committed to nxt after compute) ----
        if (t + 1 < T_) {
            if constexpr (LAYER == 0) {
                xv = src[((size_t)(n0 + (tid >> 4)) * F_ + (tid & 15)) * T_ + t + 1];
            } else {
                hv = ((const float4*)(g_h0 + ((size_t)(t + 1) * N_ + n0) * H_))[tid];
            }
        }

        // ---- gates: acc[j][pair] = b_j + sum_k Wt2[k][4u+j] * in[k][rows] ----
        ull acc0[2], acc1[2], acc2[2], acc3[2];
        acc0[0] = acc0[1] = pack2(bj[0]);
        acc1[0] = acc1[1] = pack2(bj[1]);
        acc2[0] = acc2[1] = pack2(bj[2]);
        acc3[0] = acc3[1] = pack2(bj[3]);

#pragma unroll 4
        for (int k = 0; k < KIN; k++) {
            float4 w = *(const float4*)&Wt2[k * G_ + 4 * u];
            ull w0 = pack2(w.x), w1 = pack2(w.y), w2 = pack2(w.z), w3 = pack2(w.w);
            ulonglong2 v = *(const ulonglong2*)(in2c + k * INROW_ + 2 * rg);
            fma2(acc0[0], v.x, w0); fma2(acc0[1], v.y, w0);
            fma2(acc1[0], v.x, w1); fma2(acc1[1], v.y, w1);
            fma2(acc2[0], v.x, w2); fma2(acc2[1], v.y, w2);
            fma2(acc3[0], v.x, w3); fma2(acc3[1], v.y, w3);
        }

        // ---- activations + state update for 4 rows of unit u ----
        float gi[4], gf[4], gg[4], go[4];
        {
            float2 a = unpack2(acc0[0]), b = unpack2(acc0[1]);
            gi[0] = a.x; gi[1] = a.y; gi[2] = b.x; gi[3] = b.y;
            a = unpack2(acc1[0]); b = unpack2(acc1[1]);
            gf[0] = a.x; gf[1] = a.y; gf[2] = b.x; gf[3] = b.y;
            a = unpack2(acc2[0]); b = unpack2(acc2[1]);
            gg[0] = a.x; gg[1] = a.y; gg[2] = b.x; gg[3] = b.y;
            a = unpack2(acc3[0]); b = unpack2(acc3[1]);
            go[0] = a.x; go[1] = a.y; go[2] = b.x; go[3] = b.y;
        }
        float4 hout;
        float* hp = (float*)&hout;
#pragma unroll
        for (int p = 0; p < 4; p++) {
            float c = sigf(gf[p]) * c_reg[p] + sigf(gi[p]) * tanh_f(gg[p]);
            c_reg[p] = c;
            hp[p] = sigf(go[p]) * tanh_f(c);
        }

        // ---- write h(t) into nxt buffer (STS.128, aligned) ----
        *(float4*)&nxt[(KI + u) * INROWF_ + 4 * rg] = hout;

        // ---- commit prefetched x(t+1) into nxt ----
        if (t + 1 < T_) {
            if constexpr (LAYER == 0) {
                nxt[(tid & 15) * INROWF_ + (tid >> 4)] = xv;
            } else {
                int lin = tid * 4, r = lin >> 6, k = lin & 63;
                nxt[(k + 0) * INROWF_ + r] = hv.x; nxt[(k + 1) * INROWF_ + r] = hv.y;
                nxt[(k + 2) * INROWF_ + r] = hv.z; nxt[(k + 3) * INROWF_ + r] = hv.w;
            }
        }

        // ---- global outputs ----
        if constexpr (LAYER == 0) {
#pragma unroll
            for (int p = 0; p < 4; p++)
                g_h0[((size_t)t * N_ + n0 + 4 * rg + p) * H_ + u] = hp[p];
        } else {
            if (u == 0) {
#pragma unroll
                for (int p = 0; p < 4; p++)
                    g_xs[(size_t)(n0 + 4 * rg + p) * T_ + t] = hp[p];
            }
        }

        __syncthreads();   // nxt fully written before step t+1 reads it
    }
}

// --------------------------- row stats (mu, std) ----------------------------
__global__ __launch_bounds__(256)
void stats_kernel(const float* __restrict__ xs, float* __restrict__ mu,
                  float* __restrict__ sd)
{
    __shared__ float sh[8], sh2[8];
    int n = blockIdx.x, tid = threadIdx.x;
    float s = 0.f, s2 = 0.f;
    for (int t = tid; t < T_; t += 256) {
        float v = xs[(size_t)n * T_ + t];
        s += v; s2 += v * v;
    }
#pragma unroll
    for (int o = 16; o; o >>= 1) {
        s  += __shfl_xor_sync(0xffffffffu, s, o);
        s2 += __shfl_xor_sync(0xffffffffu, s2, o);
    }
    if ((tid & 31) == 0) { sh[tid >> 5] = s; sh2[tid >> 5] = s2; }
    __syncthreads();
    if (tid == 0) {
        float ts = 0.f, ts2 = 0.f;
        for (int w = 0; w < 8; w++) { ts += sh[w]; ts2 += sh2[w]; }
        float m = ts * (1.0f / T_);
        float var = ts2 * (1.0f / T_) - m * m;
        mu[n] = m;
        sd[n] = sqrtf(fmaxf(var, 0.0f));
    }
}

// --------------------------- corr GEMM (X X^T -> adj), f32x2 ---------------
__global__ __launch_bounds__(256)
void corr_kernel(const float* __restrict__ X, float* __restrict__ adj,
                 const float* __restrict__ mu, const float* __restrict__ sd)
{
    if (blockIdx.x < blockIdx.y) return;   // symmetric: upper-triangle tiles only
    __shared__ float As[16][68];
    __shared__ float Bs[16][68];
    const int tid = threadIdx.x;
    const int tx = tid & 15, ty = tid >> 4;
    const int row0 = blockIdx.y * 64, col0 = blockIdx.x * 64;
    const int ar = tid >> 2, ac = (tid & 3) << 2;
    ull acc2[2][4];
#pragma unroll
    for (int i = 0; i < 2; i++)
#pragma unroll
        for (int j = 0; j < 4; j++) acc2[i][j] = 0ull;

    for (int k0 = 0; k0 < T_; k0 += 16) {
        float4 a4 = *(const float4*)&X[(size_t)(row0 + ar) * T_ + k0 + ac];
        As[ac + 0][ar] = a4.x; As[ac + 1][ar] = a4.y;
        As[ac + 2][ar] = a4.z; As[ac + 3][ar] = a4.w;
        float4 b4 = *(const float4*)&X[(size_t)(col0 + ar) * T_ + k0 + ac];
        Bs[ac + 0][ar] = b4.x; Bs[ac + 1][ar] = b4.y;
        Bs[ac + 2][ar] = b4.z; Bs[ac + 3][ar] = b4.w;
        __syncthreads();
#pragma unroll
        for (int k = 0; k < 16; k++) {
            float4 av = *(const float4*)&As[k][ty << 2];
            float4 bv = *(const float4*)&Bs[k][tx << 2];
            ull a01 = packab(av.x, av.y), a23 = packab(av.z, av.w);
            ull b0 = pack2(bv.x), b1 = pack2(bv.y), b2 = pack2(bv.z), b3 = pack2(bv.w);
            fma2(acc2[0][0], a01, b0); fma2(acc2[1][0], a23, b0);
            fma2(acc2[0][1], a01, b1); fma2(acc2[1][1], a23, b1);
            fma2(acc2[0][2], a01, b2); fma2(acc2[1][2], a23, b2);
            fma2(acc2[0][3], a01, b3); fma2(acc2[1][3], a23, b3);
        }
        __syncthreads();
    }
    float acc[4][4];
#pragma unroll
    for (int j = 0; j < 4; j++) {
        float2 r01 = unpack2(acc2[0][j]);
        float2 r23 = unpack2(acc2[1][j]);
        acc[0][j] = r01.x; acc[1][j] = r01.y; acc[2][j] = r23.x; acc[3][j] = r23.y;
    }
#pragma unroll
    for (int i = 0; i < 4; i++) {
        int gi = row0 + (ty << 2) + i;
        float mi = mu[gi], si = sd[gi];
#pragma unroll
        for (int j = 0; j < 4; j++) {
            int gj = col0 + (tx << 2) + j;
            float cov = acc[i][j] * (1.0f / T_) - mi * mu[gj];
            float den = si * sd[gj];
            float corr = (den == 0.0f) ? 0.0f : cov / den;
            float a = corr + ((gi == gj) ? 1.0f : 0.0f);
            adj[(size_t)gi * N_ + gj] = a;
            adj[(size_t)gj * N_ + gi] = a;
        }
    }
}

// --------------------------- rowsum -> d = rs^-0.5 --------------------------
__global__ __launch_bounds__(256)
void rowsum_kernel(const float* __restrict__ adj, float* __restrict__ dvec)
{
    __shared__ float sh[8];
    int i = blockIdx.x, tid = threadIdx.x;
    float s = 0.f;
    for (int j = tid; j < N_; j += 256) s += adj[(size_t)i * N_ + j];
#pragma unroll
    for (int o = 16; o; o >>= 1) s += __shfl_xor_sync(0xffffffffu, s, o);
    if ((tid & 31) == 0) sh[tid >> 5] = s;
    __syncthreads();
    if (tid == 0) {
        float ts = 0.f;
        for (int w = 0; w < 8; w++) ts += sh[w];
        dvec[i] = (ts > 0.0f) ? (1.0f / sqrtf(ts)) : 0.0f;
    }
}

// --------------------------- tiled GEMM (NN), f32x2, epilogues --------------
// MODE 1: C = d[i] * (A@B)
// MODE 2: C = relu(d[i] * (A@B) + bias[j])
template <int MODE>
__global__ __launch_bounds__(256)
void gemm_nn(const float* __restrict__ A, const float* __restrict__ B,
             float* __restrict__ C, int M, int N, int K,
             const float* __restrict__ dvec, const float* __restrict__ bias)
{
    __shared__ float As[16][68];
    __shared__ float Bs[16][64];
    const int tid = threadIdx.x;
    const int tx = tid & 15, ty = tid >> 4;
    const int row0 = blockIdx.y * 64, col0 = blockIdx.x * 64;
    const int ar = tid >> 2, ac = (tid & 3) << 2;
    const int br = tid >> 4, bc = (tid & 15) << 2;
    ull acc2[2][4];
#pragma unroll
    for (int i = 0; i < 2; i++)
#pragma unroll
        for (int j = 0; j < 4; j++) acc2[i][j] = 0ull;

    for (int k0 = 0; k0 < K; k0 += 16) {
        float4 a4 = *(const float4*)&A[(size_t)(row0 + ar) * K + k0 + ac];
        As[ac + 0][ar] = a4.x; As[ac + 1][ar] = a4.y;
        As[ac + 2][ar] = a4.z; As[ac + 3][ar] = a4.w;
        *(float4*)&Bs[br][bc] = *(const float4*)&B[(size_t)(k0 + br) * N + col0 + bc];
        __syncthreads();
#pragma unroll
        for (int k = 0; k < 16; k++) {
            float4 av = *(const float4*)&As[k][ty << 2];
            float4 bv = *(const float4*)&Bs[k][tx << 2];
            ull a01 = packab(av.x, av.y), a23 = packab(av.z, av.w);
            ull b0 = pack2(bv.x), b1 = pack2(bv.y), b2 = pack2(bv.z), b3 = pack2(bv.w);
            fma2(acc2[0][0], a01, b0); fma2(acc2[1][0], a23, b0);
            fma2(acc2[0][1], a01, b1); fma2(acc2[1][1], a23, b1);
            fma2(acc2[0][2], a01, b2); fma2(acc2[1][2], a23, b2);
            fma2(acc2[0][3], a01, b3); fma2(acc2[1][3], a23, b3);
        }
        __syncthreads();
    }
    float acc[4][4];
#pragma unroll
    for (int j = 0; j < 4; j++) {
        float2 r01 = unpack2(acc2[0][j]);
        float2 r23 = unpack2(acc2[1][j]);
        acc[0][j] = r01.x; acc[1][j] = r01.y; acc[2][j] = r23.x; acc[3][j] = r23.y;
    }
#pragma unroll
    for (int i = 0; i < 4; i++) {
        int gi = row0 + (ty << 2) + i;
        float dv = dvec[gi];
#pragma unroll
        for (int j = 0; j < 4; j++) {
            int gj = col0 + (tx << 2) + j;
            float v = acc[i][j];
            if (MODE == 1) v = dv * v;
            if (MODE == 2) { v = dv * v + bias[gj]; v = fmaxf(v, 0.0f); }
            C[(size_t)gi * N + gj] = v;
        }
    }
}

// --------------------------- classifier -------------------------------------
__global__ void clf_kernel(const float* __restrict__ z, const float* __restrict__ w,
                           const float* __restrict__ b, float* __restrict__ out)
{
    int idx = blockIdx.x * blockDim.x + threadIdx.x;
    if (idx >= N_ * NC_) return;
    int n = idx / NC_, c = idx - n * NC_;
    float s = b[c];
    const float* zr = z + (size_t)n * HID_;
#pragma unroll 8
    for (int h = 0; h < HID_; h++) s += zr[h] * w[h * NC_ + c];
    out[idx] = s;
}

// --------------------------- launch ------------------------------------------
extern "C" void kernel_launch(void* const* d_in, const int* in_sizes, int n_in,
                              void* d_out, int out_size)
{
    const float* features = (const float*)d_in[0];
    const float* w_ih0 = (const float*)d_in[1];
    const float* w_hh0 = (const float*)d_in[2];
    const float* b_ih0 = (const float*)d_in[3];
    const float* b_hh0 = (const float*)d_in[4];
    const float* w_ih1 = (const float*)d_in[5];
    const float* w_hh1 = (const float*)d_in[6];
    const float* b_ih1 = (const float*)d_in[7];
    const float* b_hh1 = (const float*)d_in[8];
    const float* gc1_w = (const float*)d_in[9];
    const float* gc1_b = (const float*)d_in[10];
    const float* gc2_w = (const float*)d_in[11];
    const float* gc2_b = (const float*)d_in[12];
    const float* clf_w = (const float*)d_in[13];
    const float* clf_b = (const float*)d_in[14];
    float* out = (float*)d_out;

    float *p_xs, *p_adj, *p_mu, *p_sd, *p_d, *p_y, *p_z;
    cudaGetSymbolAddress((void**)&p_xs,  g_xs);
    cudaGetSymbolAddress((void**)&p_adj, g_adj);
    cudaGetSymbolAddress((void**)&p_mu,  g_mu);
    cudaGetSymbolAddress((void**)&p_sd,  g_sd);
    cudaGetSymbolAddress((void**)&p_d,   g_d);
    cudaGetSymbolAddress((void**)&p_y,   g_y);
    cudaGetSymbolAddress((void**)&p_z,   g_z);

    const int smem0 = (80  * G_ + 2 * 80  * INROWF_) * 4;  // ~105 KB
    const int smem1 = (128 * G_ + 2 * 128 * INROWF_) * 4;  // ~168 KB
    cudaFuncSetAttribute((const void*)lstm_kernel<80, 0>,
                         cudaFuncAttributeMaxDynamicSharedMemorySize, smem0);
    cudaFuncSetAttribute((const void*)lstm_kernel<128, 1>,
                         cudaFuncAttributeMaxDynamicSharedMemorySize, smem1);

    // LSTM layer 0 (input: features) -> g_h0
    lstm_kernel<80, 0><<<N_ / R_, 512, smem0>>>(features, w_ih0, w_hh0, b_ih0, b_hh0);
    // LSTM layer 1 (input: g_h0) -> g_xs (channel 0 only)
    lstm_kernel<128, 1><<<N_ / R_, 512, smem1>>>(nullptr, w_ih1, w_hh1, b_ih1, b_hh1);

    // adjacency
    stats_kernel<<<N_, 256>>>(p_xs, p_mu, p_sd);
    corr_kernel<<<dim3(N_ / 64, N_ / 64), 256>>>(p_xs, p_adj, p_mu, p_sd);
    rowsum_kernel<<<N_, 256>>>(p_adj, p_d);

    // GCN: dad@M = D adj D M -> fold both D scalings into GEMM epilogues
    gemm_nn<1><<<dim3(HID_ / 64, N_ / 64), 256>>>(p_xs,  gc1_w, p_y, N_, HID_, T_,   p_d, nullptr);
    gemm_nn<2><<<dim3(HID_ / 64, N_ / 64), 256>>>(p_adj, p_y,   p_z, N_, HID_, N_,   p_d, gc1_b);
    gemm_nn<1><<<dim3(HID_ / 64, N_ / 64), 256>>>(p_z,   gc2_w, p_y, N_, HID_, HID_, p_d, nullptr);
    gemm_nn<2><<<dim3(HID_ / 64, N_ / 64), 256>>>(p_adj, p_y,   p_z, N_, HID_, N_,   p_d, gc2_b);

    // classifier
    clf_kernel<<<(N_ * NC_ + 255) / 256, 256>>>(p_z, clf_w, clf_b, out);
}